// round 1
// baseline (speedup 1.0000x reference)
#include <cuda_runtime.h>
#include <math.h>

// ---------------- scratch (static device globals; no allocation) ----------------
__device__ float g_part1[800 * 512];          // gemm1 partials: [(j*8+r)][chunk]
__device__ float g_tmp1[800];                 // (8,100) row-major r*100+j
__device__ float g_bn[32];                    // boxNew (8,4)
__device__ float g_feat[8 * 24576];           // pooled features (B, 3*64*128)
__device__ float g_part2[7 * 128 * 8 * 128];  // head partials: [((k*128+h)*8+r)][chunk]
__device__ float g_hidden[7 * 8 * 128];       // relu hidden (k,b,h)

// ---------------- stage 1: xf(8x65536) @ wr2_w1(65536x100), split-K ----------------
__global__ void k_gemm1_part(const float* __restrict__ x3, const float* __restrict__ w1) {
    __shared__ float xs[8 * 128];
    const int bx = blockIdx.x;           // 512 K-chunks of 128
    const int k0 = bx * 128;
    const int tid = threadIdx.x;
    for (int t = tid; t < 1024; t += 128) {
        int r = t >> 7, kk = t & 127;
        xs[t] = x3[r * 65536 + k0 + kk];
    }
    __syncthreads();
    if (tid < 100) {
        float acc[8] = {0.f, 0.f, 0.f, 0.f, 0.f, 0.f, 0.f, 0.f};
        for (int kk = 0; kk < 128; kk += 4) {
            float w0 = w1[(k0 + kk + 0) * 100 + tid];
            float wv1 = w1[(k0 + kk + 1) * 100 + tid];
            float wv2 = w1[(k0 + kk + 2) * 100 + tid];
            float wv3 = w1[(k0 + kk + 3) * 100 + tid];
#pragma unroll
            for (int r = 0; r < 8; r++) {
                float4 f = *(const float4*)&xs[r * 128 + kk];
                acc[r] = fmaf(f.x, w0, fmaf(f.y, wv1, fmaf(f.z, wv2, fmaf(f.w, wv3, acc[r]))));
            }
        }
#pragma unroll
        for (int r = 0; r < 8; r++) g_part1[(tid * 8 + r) * 512 + bx] = acc[r];
    }
}

__global__ void k_reduce_g1(const float* __restrict__ b1) {
    int w = (blockIdx.x * blockDim.x + threadIdx.x) >> 5;  // warp per output, 800 warps
    int lane = threadIdx.x & 31;
    if (w >= 800) return;
    const float* p = &g_part1[w * 512];
    float s = 0.f;
#pragma unroll
    for (int q = 0; q < 16; q++) s += p[lane + q * 32];
#pragma unroll
    for (int o = 16; o; o >>= 1) s += __shfl_down_sync(0xffffffffu, s, o);
    if (lane == 0) {
        int j = w >> 3, r = w & 7;
        g_tmp1[r * 100 + j] = s + b1[j];
    }
}

// ---------------- stage 2: tiny MLP -> boxLoc -> boxNew (clipped) ----------------
__global__ void k_mlp_box(const float* __restrict__ w2, const float* __restrict__ b2,
                          const float* __restrict__ w3, const float* __restrict__ b3) {
    __shared__ float t1[800], t2[800], bl[32];
    const int tid = threadIdx.x;
    for (int t = tid; t < 800; t += 128) t1[t] = g_tmp1[t];
    __syncthreads();
    if (tid < 100) {
        for (int b = 0; b < 8; b++) {
            float acc = b2[tid];
            for (int i = 0; i < 100; i++) acc = fmaf(t1[b * 100 + i], w2[i * 100 + tid], acc);
            t2[b * 100 + tid] = acc;
        }
    }
    __syncthreads();
    if (tid < 32) {
        int b = tid >> 2, cc = tid & 3;
        float acc = b3[cc];
        for (int i = 0; i < 100; i++) acc = fmaf(t2[b * 100 + i], w3[i * 4 + cc], acc);
        bl[tid] = acc;
    }
    __syncthreads();
    if (tid < 32) {
        int b = tid >> 2, cc = tid & 3;
        float b0 = bl[b * 4 + 0], bb1 = bl[b * 4 + 1], bb2 = bl[b * 4 + 2], bb3 = bl[b * 4 + 3];
        float v;
        if (cc == 0)      v = b0 - 0.5f * bb2;
        else if (cc == 1) v = bb1 - 0.5f * bb3;
        else if (cc == 2) v = b0 + 0.5f * bb2;
        else              v = bb1 + 0.5f * bb3;
        g_bn[b * 4 + cc] = fminf(fmaxf(v, 0.0f), 1.0f);
    }
}

// ---------------- stage 3: adaptive ROI max-pool to (16,8) over 3 scales ----------------
__global__ void k_roi(const float* __restrict__ x1p, const float* __restrict__ x2p,
                      const float* __restrict__ x3p) {
    const int bx = blockIdx.x;        // 3*8*64 = 1536
    const int s = bx >> 9;
    const int rem = bx & 511;
    const int b = rem >> 6, c = rem & 63;
    const int HW = (s == 0) ? 128 : (s == 1) ? 64 : 32;
    const float* xp = (s == 0) ? x1p : (s == 1) ? x2p : x3p;

    const float bn0 = g_bn[b * 4 + 0], bn1 = g_bn[b * 4 + 1];
    const float bn2 = g_bn[b * 4 + 2], bn3 = g_bn[b * 4 + 3];
    const float Sf = (float)HW;
    const int X1 = (int)floorf(bn0 * Sf), Y1 = (int)floorf(bn1 * Sf);
    const int X2 = (int)floorf(bn2 * Sf), Y2 = (int)floorf(bn3 * Sf);
    const bool valid = (X1 >= 0) && (Y1 >= 0) && (X2 < HW) && (Y2 < HW) && (X2 > X1) && (Y2 > Y1);

    const int tid = threadIdx.x;  // 128 = 16x8 bins
    float out = 0.0f;
    if (valid) {
        const int h = Y2 - Y1 + 1, w = X2 - X1 + 1;
        const int i = tid >> 3, j = tid & 7;
        const int lo_i = (i * h) >> 4, hi_i = ((i + 1) * h + 15) >> 4;
        const int lo_j = (j * w) >> 3, hi_j = ((j + 1) * w + 7) >> 3;
        float m = -3.0e38f;
        const float* base = xp + ((size_t)(b * 64 + c) * HW + Y1) * HW + X1;
        for (int y = lo_i; y < hi_i; y++) {
            const float* row = base + y * HW;
            for (int xx = lo_j; xx < hi_j; xx++) m = fmaxf(m, row[xx]);
        }
        out = m;
    }
    g_feat[b * 24576 + (s * 64 + c) * 128 + tid] = out;
}

// ---------------- stage 4: feat(8x24576) @ head_w1[k](24576x128), split-K x7 ----------------
__global__ void k_head_part(const float* __restrict__ hw) {
    __shared__ float fs[8 * 192];
    const int bx = blockIdx.x;       // 7 * 128 chunks
    const int k = bx >> 7, ch = bx & 127;
    const int d0 = ch * 192;
    const int tid = threadIdx.x;     // h = tid (128)
    for (int t = tid; t < 1536; t += 128) {
        int r = t / 192, dd = t % 192;
        fs[t] = g_feat[r * 24576 + d0 + dd];
    }
    __syncthreads();
    float acc[8] = {0.f, 0.f, 0.f, 0.f, 0.f, 0.f, 0.f, 0.f};
    const float* wb = hw + (size_t)(k * 24576 + d0) * 128 + tid;
    for (int d = 0; d < 192; d += 4) {
        float w0 = wb[(d + 0) * 128];
        float wv1 = wb[(d + 1) * 128];
        float wv2 = wb[(d + 2) * 128];
        float wv3 = wb[(d + 3) * 128];
#pragma unroll
        for (int r = 0; r < 8; r++) {
            float4 f = *(const float4*)&fs[r * 192 + d];
            acc[r] = fmaf(f.x, w0, fmaf(f.y, wv1, fmaf(f.z, wv2, fmaf(f.w, wv3, acc[r]))));
        }
    }
#pragma unroll
    for (int r = 0; r < 8; r++) g_part2[((k * 128 + tid) * 8 + r) * 128 + ch] = acc[r];
}

__global__ void k_reduce_head(const float* __restrict__ hb) {
    int w = (blockIdx.x * blockDim.x + threadIdx.x) >> 5;  // warp per output, 7168 warps
    int lane = threadIdx.x & 31;
    if (w >= 7168) return;
    const float* p = &g_part2[w * 128];
    float s = 0.f;
#pragma unroll
    for (int q = 0; q < 4; q++) s += p[lane + q * 32];
#pragma unroll
    for (int o = 16; o; o >>= 1) s += __shfl_down_sync(0xffffffffu, s, o);
    if (lane == 0) {
        int k = w >> 10, rem = w & 1023, h = rem >> 3, r = rem & 7;
        float v = s + hb[k * 128 + h];
        g_hidden[(k * 8 + r) * 128 + h] = fmaxf(v, 0.0f);
    }
}

// ---------------- stage 5: output heads ----------------
__global__ void k_final(const float* __restrict__ wp, const float* __restrict__ bp,
                        const float* __restrict__ wa, const float* __restrict__ ba,
                        const float* __restrict__ wad, const float* __restrict__ bad,
                        float* __restrict__ out) {
    const int k = blockIdx.x;   // 7 heads
    int O, off;
    const float *Wk, *Bk;
    if (k == 0)      { O = 38; Wk = wp; Bk = bp; off = 0; }
    else if (k == 1) { O = 25; Wk = wa; Bk = ba; off = 304; }
    else             { O = 35; Wk = wad + (k - 2) * 128 * 35; Bk = bad + (k - 2) * 35;
                       off = 504 + (k - 2) * 280; }
    const int tid = threadIdx.x;
    if (tid < 8 * O) {
        int b = tid / O, o = tid % O;
        float acc = Bk[o];
        const float* hr = &g_hidden[(k * 8 + b) * 128];
        for (int h = 0; h < 128; h++) acc = fmaf(hr[h], Wk[h * O + o], acc);
        out[off + b * O + o] = acc;
    }
}

// ---------------- launch ----------------
extern "C" void kernel_launch(void* const* d_in, const int* in_sizes, int n_in,
                              void* d_out, int out_size) {
    (void)in_sizes; (void)n_in; (void)out_size;
    const float* x1 = (const float*)d_in[0];
    const float* x2 = (const float*)d_in[1];
    const float* x3 = (const float*)d_in[2];
    // d_in[3] detection_targets, d_in[4] YI: unused
    const float* w1 = (const float*)d_in[5];
    const float* b1 = (const float*)d_in[6];
    const float* w2 = (const float*)d_in[7];
    const float* b2 = (const float*)d_in[8];
    const float* w3 = (const float*)d_in[9];
    const float* b3 = (const float*)d_in[10];
    const float* hw = (const float*)d_in[11];
    const float* hb = (const float*)d_in[12];
    const float* wp = (const float*)d_in[13];
    const float* bp = (const float*)d_in[14];
    const float* wa = (const float*)d_in[15];
    const float* ba = (const float*)d_in[16];
    const float* wad = (const float*)d_in[17];
    const float* bad = (const float*)d_in[18];
    float* out = (float*)d_out;

    k_gemm1_part<<<512, 128>>>(x3, w1);
    k_reduce_g1<<<100, 256>>>(b1);
    k_mlp_box<<<1, 128>>>(w2, b2, w3, b3);
    k_roi<<<1536, 128>>>(x1, x2, x3);
    k_head_part<<<896, 128>>>(hw);
    k_reduce_head<<<896, 256>>>(hb);
    k_final<<<7, 320>>>(wp, bp, wa, ba, wad, bad, out);
}